// round 1
// baseline (speedup 1.0000x reference)
#include <cuda_runtime.h>
#include <cstdint>
#include <cstddef>

#define NROWS 4096
#define KDIM  4096
#define CNUM  20

// ---------------- device scratch (no allocations allowed) ----------------
__device__ float g_Wpack1[KDIM * 64];          // cols 0..19 Wcls, 20..40 Wr1, 41..61 Wr2, 62..63 zero
__device__ float g_Wpack2[KDIM * 32];          // cols 0..19 Wdet, 20..31 zero
__device__ float g_C1part[4][NROWS * 64];      // split-K partials, GEMM1
__device__ float g_C2part[4][NROWS * 32];      // split-K partials, GEMM2 (det)
__device__ float g_cls_score[NROWS * CNUM];
__device__ float g_cls_prob [NROWS * CNUM];
__device__ float g_r1_prob  [NROWS * 21];
__device__ float g_r2_prob  [NROWS * 21];
__device__ float g_dcs[CNUM];
__device__ float g_boxes1[CNUM * 4];
__device__ float g_boxes2[CNUM * 4];
__device__ float g_lpart[16 * 4];              // per-block (loss1, cnt1, loss2, cnt2)

// ---------------- weight packing ----------------
__global__ void k_pack(const float* __restrict__ Wcls, const float* __restrict__ Wr1,
                       const float* __restrict__ Wr2,  const float* __restrict__ Wdet) {
    int idx = blockIdx.x * 256 + threadIdx.x;   // grid covers 4096*96 exactly
    if (idx < KDIM * 64) {
        int k = idx >> 6, c = idx & 63;
        float v = 0.f;
        if      (c < 20) v = Wcls[k * 20 + c];
        else if (c < 41) v = Wr1 [k * 21 + (c - 20)];
        else if (c < 62) v = Wr2 [k * 21 + (c - 41)];
        g_Wpack1[idx] = v;
    } else {
        int j = idx - KDIM * 64;
        int k = j >> 5, c = j & 31;
        g_Wpack2[j] = (c < 20) ? Wdet[k * 20 + c] : 0.f;
    }
}

// ---------------- fused GEMM: blocks 0..255 -> roi GEMM, 256..511 -> (frame-ctx) GEMM ----
__global__ __launch_bounds__(256) void k_gemm(const float* __restrict__ roi,
                                              const float* __restrict__ ctx,
                                              const float* __restrict__ frm) {
    __shared__ __align__(16) float Ash[64][36];
    __shared__ __align__(16) float Wsh[32][64];
    int tid = threadIdx.x;
    int b   = blockIdx.x;

    if (b < 256) {
        // ---- GEMM1: C1[4096,64] = roi @ Wpack1, split-K x4, tile 64x64x32 ----
        int rowblk = b >> 2, ks = b & 3;
        int row0 = rowblk * 64;
        int k0   = ks * 1024;
        int tx = tid & 15, ty = tid >> 4;           // tx: 16 col groups of 4, ty: 16 row groups of 4
        float acc[4][4] = {};
        for (int kt = 0; kt < 1024; kt += 32) {
            #pragma unroll
            for (int L = 0; L < 2; L++) {
                int lin = tid + L * 256;
                int r = lin >> 3, kq = lin & 7;
                float4 v = *(const float4*)(roi + (size_t)(row0 + r) * KDIM + k0 + kt + kq * 4);
                *(float4*)&Ash[r][kq * 4] = v;
            }
            #pragma unroll
            for (int L = 0; L < 2; L++) {
                int lin = tid + L * 256;
                int kr = lin >> 4, cq = lin & 15;
                float4 v = *(const float4*)(g_Wpack1 + (size_t)(k0 + kt + kr) * 64 + cq * 4);
                *(float4*)&Wsh[kr][cq * 4] = v;
            }
            __syncthreads();
            #pragma unroll
            for (int kk = 0; kk < 32; kk++) {
                float4 w = *(float4*)&Wsh[kk][tx * 4];
                #pragma unroll
                for (int i = 0; i < 4; i++) {
                    float a = Ash[ty * 4 + i][kk];
                    acc[i][0] += a * w.x; acc[i][1] += a * w.y;
                    acc[i][2] += a * w.z; acc[i][3] += a * w.w;
                }
            }
            __syncthreads();
        }
        #pragma unroll
        for (int i = 0; i < 4; i++) {
            *(float4*)&g_C1part[ks][(size_t)(row0 + ty * 4 + i) * 64 + tx * 4] =
                make_float4(acc[i][0], acc[i][1], acc[i][2], acc[i][3]);
        }
    } else {
        // ---- GEMM2: C2[4096,32] = (frame - ctx) @ Wpack2, split-K x4, tile 64x32x32 ----
        int b2 = b - 256;
        int rowblk = b2 >> 2, ks = b2 & 3;
        int row0 = rowblk * 64;
        int k0   = ks * 1024;
        int tx = tid & 7, ty = tid >> 3;            // tx: 8 col groups of 4, ty: 32 row groups of 2
        float acc[2][4] = {};
        for (int kt = 0; kt < 1024; kt += 32) {
            #pragma unroll
            for (int L = 0; L < 2; L++) {
                int lin = tid + L * 256;
                int r = lin >> 3, kq = lin & 7;
                size_t off = (size_t)(row0 + r) * KDIM + k0 + kt + kq * 4;
                float4 f = *(const float4*)(frm + off);
                float4 c = *(const float4*)(ctx + off);
                *(float4*)&Ash[r][kq * 4] = make_float4(f.x - c.x, f.y - c.y, f.z - c.z, f.w - c.w);
            }
            {
                int kr = tid >> 3, cq = tid & 7;
                float4 v = *(const float4*)(g_Wpack2 + (size_t)(k0 + kt + kr) * 32 + cq * 4);
                *(float4*)&Wsh[kr][cq * 4] = v;
            }
            __syncthreads();
            #pragma unroll
            for (int kk = 0; kk < 32; kk++) {
                float4 w = *(float4*)&Wsh[kk][tx * 4];
                #pragma unroll
                for (int i = 0; i < 2; i++) {
                    float a = Ash[ty * 2 + i][kk];
                    acc[i][0] += a * w.x; acc[i][1] += a * w.y;
                    acc[i][2] += a * w.z; acc[i][3] += a * w.w;
                }
            }
            __syncthreads();
        }
        #pragma unroll
        for (int i = 0; i < 2; i++) {
            *(float4*)&g_C2part[ks][(size_t)(row0 + ty * 2 + i) * 32 + tx * 4] =
                make_float4(acc[i][0], acc[i][1], acc[i][2], acc[i][3]);
        }
    }
}

// ---------------- E1: reduce split-K, add bias, row softmaxes (cls / r1 / r2) ----------
__global__ void k_rowsoft(const float* __restrict__ bcls, const float* __restrict__ br1,
                          const float* __restrict__ br2) {
    __shared__ float sv[8][64];
    __shared__ float sms[8][6];   // per row: (max,sum) x 3 groups
    int tid = threadIdx.x;
    int w = tid >> 5, lane = tid & 31;
    int r = blockIdx.x * 8 + w;
    size_t ro = (size_t)r * 64;
    #pragma unroll
    for (int h = 0; h < 2; h++) {
        int c = lane + 32 * h;
        if (c < 62) {
            float s = g_C1part[0][ro + c] + g_C1part[1][ro + c] +
                      g_C1part[2][ro + c] + g_C1part[3][ro + c];
            if (c < 20)      { s += bcls[c];      g_cls_score[r * 20 + c] = s; }
            else if (c < 41) { s += br1[c - 20]; }
            else             { s += br2[c - 41]; }
            sv[w][c] = s;
        }
    }
    __syncwarp();
    if (lane < 3) {
        int c0  = (lane == 0) ? 0 : (lane == 1 ? 20 : 41);
        int cnt = (lane == 0) ? 20 : 21;
        float m = -1e30f;
        for (int i = 0; i < cnt; i++) m = fmaxf(m, sv[w][c0 + i]);
        float s = 0.f;
        for (int i = 0; i < cnt; i++) s += expf(sv[w][c0 + i] - m);
        sms[w][lane * 2] = m; sms[w][lane * 2 + 1] = s;
    }
    __syncwarp();
    #pragma unroll
    for (int h = 0; h < 2; h++) {
        int c = lane + 32 * h;
        if (c < 62) {
            int g = (c < 20) ? 0 : ((c < 41) ? 1 : 2);
            float p = expf(sv[w][c] - sms[w][g * 2]) / sms[w][g * 2 + 1];
            if (g == 0)      g_cls_prob[r * 20 + c] = p;
            else if (g == 1) g_r1_prob[r * 21 + (c - 20)] = p;
            else             g_r2_prob[r * 21 + (c - 41)] = p;
        }
    }
}

// ---------------- E2: per-class column pass ----------------
// det softmax over N, det_cls_score, argmax of p1 = cls_prob*det_prob*ISw (sup.1)
// and p2 = r1_prob[:, c+1]*ISw (sup.2, column-0 dropped) -> pick boxes.
__global__ void k_colreduce(const float* __restrict__ ISw, const float* __restrict__ ss) {
    __shared__ float sred[256];
    __shared__ int   sidx[256];
    int c = blockIdx.x, tid = threadIdx.x;
    float dv[16];
    float tmax = -1e30f;
    #pragma unroll
    for (int t = 0; t < 16; t++) {
        int n = tid + t * 256;
        float s = g_C2part[0][n * 32 + c] + g_C2part[1][n * 32 + c] +
                  g_C2part[2][n * 32 + c] + g_C2part[3][n * 32 + c];
        dv[t] = s;
        tmax = fmaxf(tmax, s);
    }
    sred[tid] = tmax; __syncthreads();
    for (int s = 128; s > 0; s >>= 1) { if (tid < s) sred[tid] = fmaxf(sred[tid], sred[tid + s]); __syncthreads(); }
    float M = sred[0]; __syncthreads();

    float bsum = 0.f;
    #pragma unroll
    for (int t = 0; t < 16; t++) { float e = expf(dv[t] - M); dv[t] = e; bsum += e; }
    sred[tid] = bsum; __syncthreads();
    for (int s = 128; s > 0; s >>= 1) { if (tid < s) sred[tid] += sred[tid + s]; __syncthreads(); }
    float inv = 1.0f / sred[0]; __syncthreads();

    float dcs = 0.f, bv1 = -1e30f, bv2 = -1e30f;
    int bi1 = 0, bi2 = 0;
    #pragma unroll
    for (int t = 0; t < 16; t++) {
        int n = tid + t * 256;                   // ascending n per thread -> first-occurrence ties
        float dp = dv[t] * inv;
        dcs += g_cls_score[n * 20 + c] * dp;
        float isw = ISw[n];
        float p1 = g_cls_prob[n * 20 + c] * dp * isw;
        if (p1 > bv1) { bv1 = p1; bi1 = n; }
        float p2 = g_r1_prob[n * 21 + c + 1] * isw;
        if (p2 > bv2) { bv2 = p2; bi2 = n; }
    }
    sred[tid] = dcs; __syncthreads();
    for (int s = 128; s > 0; s >>= 1) { if (tid < s) sred[tid] += sred[tid + s]; __syncthreads(); }
    if (tid == 0) g_dcs[c] = sred[0];
    __syncthreads();

    sred[tid] = bv1; sidx[tid] = bi1; __syncthreads();
    for (int s = 128; s > 0; s >>= 1) {
        if (tid < s) {
            float v = sred[tid + s]; int i = sidx[tid + s];
            if (v > sred[tid] || (v == sred[tid] && i < sidx[tid])) { sred[tid] = v; sidx[tid] = i; }
        }
        __syncthreads();
    }
    if (tid == 0) {
        int i = sidx[0];
        g_boxes1[c * 4 + 0] = ss[i * 5 + 1]; g_boxes1[c * 4 + 1] = ss[i * 5 + 2];
        g_boxes1[c * 4 + 2] = ss[i * 5 + 3]; g_boxes1[c * 4 + 3] = ss[i * 5 + 4];
    }
    __syncthreads();

    sred[tid] = bv2; sidx[tid] = bi2; __syncthreads();
    for (int s = 128; s > 0; s >>= 1) {
        if (tid < s) {
            float v = sred[tid + s]; int i = sidx[tid + s];
            if (v > sred[tid] || (v == sred[tid] && i < sidx[tid])) { sred[tid] = v; sidx[tid] = i; }
        }
        __syncthreads();
    }
    if (tid == 0) {
        int i = sidx[0];
        g_boxes2[c * 4 + 0] = ss[i * 5 + 1]; g_boxes2[c * 4 + 1] = ss[i * 5 + 2];
        g_boxes2[c * 4 + 2] = ss[i * 5 + 3]; g_boxes2[c * 4 + 3] = ss[i * 5 + 4];
    }
}

// ---------------- E4: per-row IoU supervision + refine-loss partial sums --------------
__global__ void k_loss(const float* __restrict__ ss, const float* __restrict__ ISw,
                       const int* __restrict__ lab) {
    __shared__ float s0[256], s1[256], s2[256], s3[256];
    int tid = threadIdx.x;
    int n = blockIdx.x * 256 + tid;
    float x1 = ss[n * 5 + 1], y1 = ss[n * 5 + 2], x2 = ss[n * 5 + 3], y2 = ss[n * 5 + 4];
    float an = (x2 - x1 + 1.f) * (y2 - y1 + 1.f);
    float mo1 = -1.f, mo2 = -1.f;
    int gt1 = 0, gt2 = 0;
    #pragma unroll
    for (int c = 0; c < 20; c++) {
        if (lab[c] == 1) {
            {
                float qx1 = g_boxes1[c * 4 + 0], qy1 = g_boxes1[c * 4 + 1];
                float qx2 = g_boxes1[c * 4 + 2], qy2 = g_boxes1[c * 4 + 3];
                float iw = fmaxf(fminf(x2, qx2) - fmaxf(x1, qx1) + 1.f, 0.f);
                float ih = fmaxf(fminf(y2, qy2) - fmaxf(y1, qy1) + 1.f, 0.f);
                float inter = iw * ih;
                float aq = (qx2 - qx1 + 1.f) * (qy2 - qy1 + 1.f);
                float iou = inter / (an + aq - inter);
                if (iou > mo1) { mo1 = iou; gt1 = c; }
            }
            {
                float qx1 = g_boxes2[c * 4 + 0], qy1 = g_boxes2[c * 4 + 1];
                float qx2 = g_boxes2[c * 4 + 2], qy2 = g_boxes2[c * 4 + 3];
                float iw = fmaxf(fminf(x2, qx2) - fmaxf(x1, qx1) + 1.f, 0.f);
                float ih = fmaxf(fminf(y2, qy2) - fmaxf(y1, qy1) + 1.f, 0.f);
                float inter = iw * ih;
                float aq = (qx2 - qx1 + 1.f) * (qy2 - qy1 + 1.f);
                float iou = inter / (an + aq - inter);
                if (iou > mo2) { mo2 = iou; gt2 = c; }
            }
        }
    }
    float isw = ISw[n];
    bool fg1 = mo1 > 0.5f;
    bool keep1 = fg1 || (mo1 >= 0.1f && mo1 < 0.5f);
    int col1 = fg1 ? gt1 + 1 : 0;
    float l1 = keep1 ? isw * logf(g_r1_prob[n * 21 + col1]) : 0.f;
    float k1 = keep1 ? 1.f : 0.f;
    bool fg2 = mo2 > 0.5f;
    bool keep2 = fg2 || (mo2 >= 0.1f && mo2 < 0.5f);
    int col2 = fg2 ? gt2 + 1 : 0;
    float l2 = keep2 ? isw * logf(g_r2_prob[n * 21 + col2]) : 0.f;
    float k2 = keep2 ? 1.f : 0.f;

    s0[tid] = l1; s1[tid] = k1; s2[tid] = l2; s3[tid] = k2;
    __syncthreads();
    for (int s = 128; s > 0; s >>= 1) {
        if (tid < s) { s0[tid] += s0[tid + s]; s1[tid] += s1[tid + s];
                       s2[tid] += s2[tid + s]; s3[tid] += s3[tid + s]; }
        __syncthreads();
    }
    if (tid == 0) {
        g_lpart[blockIdx.x * 4 + 0] = s0[0];
        g_lpart[blockIdx.x * 4 + 1] = s1[0];
        g_lpart[blockIdx.x * 4 + 2] = s2[0];
        g_lpart[blockIdx.x * 4 + 3] = s3[0];
    }
}

// ---------------- E5: final scalar ----------------
__global__ void k_final(const int* __restrict__ lab, float* __restrict__ out) {
    if (threadIdx.x == 0) {
        float S1 = 0, N1 = 0, S2 = 0, N2 = 0;
        for (int b = 0; b < 16; b++) {
            S1 += g_lpart[b * 4 + 0]; N1 += g_lpart[b * 4 + 1];
            S2 += g_lpart[b * 4 + 2]; N2 += g_lpart[b * 4 + 3];
        }
        float cd = 0.f;
        for (int c = 0; c < 20; c++) {
            float l = (float)lab[c];
            cd += fmaxf(0.f, 1.f - l * g_dcs[c]);
        }
        cd /= 20.f;
        out[0] = cd + 0.1f * (-S1 / N1) + 0.1f * (-S2 / N2);
    }
}

extern "C" void kernel_launch(void* const* d_in, const int* in_sizes, int n_in,
                              void* d_out, int out_size) {
    const float* roi  = (const float*)d_in[0];
    const float* ctx  = (const float*)d_in[1];
    const float* frm  = (const float*)d_in[2];
    const float* Wcls = (const float*)d_in[3];
    const float* bcls = (const float*)d_in[4];
    const float* Wdet = (const float*)d_in[5];
    // d_in[6] = b_det: cancels in det_score, unused
    const float* Wr1  = (const float*)d_in[7];
    const float* br1  = (const float*)d_in[8];
    const float* Wr2  = (const float*)d_in[9];
    const float* br2  = (const float*)d_in[10];
    const float* ss   = (const float*)d_in[11];
    const float* isw  = (const float*)d_in[12];
    const int*   lab  = (const int*)d_in[13];
    float* out = (float*)d_out;

    k_pack     <<<1536, 256>>>(Wcls, Wr1, Wr2, Wdet);
    k_gemm     <<<512,  256>>>(roi, ctx, frm);
    k_rowsoft  <<<512,  256>>>(bcls, br1, br2);
    k_colreduce<<<20,   256>>>(isw, ss);
    k_loss     <<<16,   256>>>(ss, isw, lab);
    k_final    <<<1,    32>>>(lab, out);
}

// round 4
// speedup vs baseline: 1.5267x; 1.5267x over previous
#include <cuda_runtime.h>
#include <cuda_bf16.h>
#include <cstdint>
#include <cstddef>

#define KD 4096
#define NR 4096

// ---------------- device scratch ----------------
__device__ __nv_bfloat16 g_W1hi[KD * 64], g_W1lo[KD * 64];
__device__ __nv_bfloat16 g_W2hi[KD * 32], g_W2lo[KD * 32];
__device__ float g_C1part[4][NR * 64];
__device__ float g_C2part[4][NR * 32];
__device__ float g_clsST[20 * NR];
__device__ float g_clsPT[20 * NR];
__device__ float g_r1T[21 * NR];
__device__ float g_r2T[21 * NR];
__device__ float g_detT[20 * NR];
__device__ float g_dcs[20];
__device__ float g_boxes1[80], g_boxes2[80];
__device__ float g_lpart[64];

// ---------------- PTX helpers ----------------
__device__ __forceinline__ uint32_t s2u(const void* p) {
    uint32_t a;
    asm("{ .reg .u64 t; cvta.to.shared.u64 t, %1; cvt.u32.u64 %0, t; }" : "=r"(a) : "l"(p));
    return a;
}
__device__ __forceinline__ void ldsm4t(uint32_t* r, uint32_t a) {
    asm volatile("ldmatrix.sync.aligned.m8n8.x4.trans.shared.b16 {%0,%1,%2,%3},[%4];"
                 : "=r"(r[0]), "=r"(r[1]), "=r"(r[2]), "=r"(r[3]) : "r"(a));
}
__device__ __forceinline__ void mma_bf16(float* d, const uint32_t* a, const uint32_t* b) {
    asm volatile("mma.sync.aligned.m16n8k16.row.col.f32.bf16.bf16.f32 "
                 "{%0,%1,%2,%3},{%4,%5,%6,%7},{%8,%9},{%0,%1,%2,%3};"
                 : "+f"(d[0]), "+f"(d[1]), "+f"(d[2]), "+f"(d[3])
                 : "r"(a[0]), "r"(a[1]), "r"(a[2]), "r"(a[3]), "r"(b[0]), "r"(b[1]));
}
__device__ __forceinline__ void cpasync16(uint32_t s, const void* g) {
    asm volatile("cp.async.cg.shared.global [%0],[%1],16;" :: "r"(s), "l"(g));
}
__device__ __forceinline__ void cvt_hilo(float2 v, uint32_t& hi, uint32_t& lo) {
    __nv_bfloat162 h = __floats2bfloat162_rn(v.x, v.y);
    float lx = v.x - __bfloat162float(h.x);
    float ly = v.y - __bfloat162float(h.y);
    __nv_bfloat162 l = __floats2bfloat162_rn(lx, ly);
    hi = *reinterpret_cast<uint32_t*>(&h);
    lo = *reinterpret_cast<uint32_t*>(&l);
}

// ---------------- k_pack: weights -> bf16 hi/lo, [k][c] rows ----------------
__global__ void k_pack(const float* __restrict__ Wcls, const float* __restrict__ Wr1,
                       const float* __restrict__ Wr2,  const float* __restrict__ Wdet) {
    int idx = blockIdx.x * 256 + threadIdx.x;   // 4096*96
    int k = idx / 96, c = idx % 96;
    float v = 0.f;
    if (c < 64) {
        if      (c < 20) v = Wcls[k * 20 + c];
        else if (c < 41) v = Wr1[k * 21 + (c - 20)];
        else if (c < 62) v = Wr2[k * 21 + (c - 41)];
        __nv_bfloat16 h = __float2bfloat16_rn(v);
        g_W1hi[k * 64 + c] = h;
        g_W1lo[k * 64 + c] = __float2bfloat16_rn(v - __bfloat162float(h));
    } else {
        int c2 = c - 64;
        if (c2 < 20) v = Wdet[k * 20 + c2];
        __nv_bfloat16 h = __float2bfloat16_rn(v);
        g_W2hi[k * 32 + c2] = h;
        g_W2lo[k * 32 + c2] = __float2bfloat16_rn(v - __bfloat162float(h));
    }
}

// ---------------- GEMM core: A from gmem in fragment layout, B via cp.async smem -------
// smem (per stage): B_hi 64 x SB bytes, B_lo at +64*SB.  2 stages.
template <int NC, bool DIFF>
__device__ __forceinline__ void gemm_core(const float* __restrict__ A1,
                                          const float* __restrict__ A2,
                                          const __nv_bfloat16* __restrict__ Whi,
                                          const __nv_bfloat16* __restrict__ Wlo,
                                          float* __restrict__ Cpart,
                                          int row0, int kbase, uint8_t* sm) {
    constexpr int SB    = (NC == 64) ? 144 : 80;
    constexpr int NSEG  = NC / 8;
    constexpr int BLO   = 64 * SB;
    constexpr int STAGE = 2 * 64 * SB;
    constexpr int NT  = NC / 2;
    constexpr int NBJ = NT / 8;
    constexpr int NQ  = NT / 16;

    const int tid = threadIdx.x, lane = tid & 31, wid = tid >> 5;
    const int rows0 = (wid & 3) * 32, ncol0 = (wid >> 2) * NT;
    const int fr = lane >> 2, fc = (lane & 3) * 2;
    uint32_t sbase = s2u(sm);
    const uint32_t laneB = ((lane & 7) + 8 * ((lane >> 3) & 1)) * SB + (lane >> 4) * 16;

    auto ldB = [&](int ch, int st) {
        uint32_t bb = sbase + st * STAGE;
        #pragma unroll
        for (int q = 0; q < (2 * 64 * NSEG) / 256; q++) {
            int i = tid + q * 256;
            bool lo = i >= 64 * NSEG;
            int ii = lo ? i - 64 * NSEG : i;
            int row = ii / NSEG, seg = ii % NSEG;
            cpasync16(bb + (lo ? BLO : 0) + row * SB + seg * 16,
                      (lo ? Wlo : Whi) + (size_t)(kbase + ch * 64 + row) * NC + seg * 8);
        }
        asm volatile("cp.async.commit_group;" ::: "memory");
    };

    float acc[2][NBJ][4] = {};

    ldB(0, 0);

    for (int ch = 0; ch < 16; ch++) {
        int st = ch & 1;
        if (ch < 15) {
            ldB(ch + 1, st ^ 1);
            asm volatile("cp.async.wait_group 1;" ::: "memory");
        } else {
            asm volatile("cp.async.wait_group 0;" ::: "memory");
        }
        __syncthreads();
        uint32_t stb = sbase + st * STAGE;
        int kc = kbase + ch * 64;

        #pragma unroll
        for (int h = 0; h < 2; h++) {
            uint32_t ah[2][2][4], al[2][2][4];
            #pragma unroll
            for (int ms = 0; ms < 2; ms++)
                #pragma unroll
                for (int kh = 0; kh < 2; kh++) {
                    int k16 = h * 2 + kh;
                    size_t ro = (size_t)(row0 + rows0 + ms * 16 + fr) * KD + kc + k16 * 16 + fc;
                    float2 v0 = *(const float2*)(A1 + ro);
                    float2 v1 = *(const float2*)(A1 + ro + 8 * (size_t)KD);
                    float2 v2 = *(const float2*)(A1 + ro + 8);
                    float2 v3 = *(const float2*)(A1 + ro + 8 * (size_t)KD + 8);
                    if (DIFF) {
                        float2 w0 = *(const float2*)(A2 + ro);
                        float2 w1 = *(const float2*)(A2 + ro + 8 * (size_t)KD);
                        float2 w2 = *(const float2*)(A2 + ro + 8);
                        float2 w3 = *(const float2*)(A2 + ro + 8 * (size_t)KD + 8);
                        v0.x -= w0.x; v0.y -= w0.y; v1.x -= w1.x; v1.y -= w1.y;
                        v2.x -= w2.x; v2.y -= w2.y; v3.x -= w3.x; v3.y -= w3.y;
                    }
                    cvt_hilo(v0, ah[ms][kh][0], al[ms][kh][0]);
                    cvt_hilo(v1, ah[ms][kh][1], al[ms][kh][1]);
                    cvt_hilo(v2, ah[ms][kh][2], al[ms][kh][2]);
                    cvt_hilo(v3, ah[ms][kh][3], al[ms][kh][3]);
                }
            #pragma unroll
            for (int kh = 0; kh < 2; kh++) {
                int k16 = h * 2 + kh;
                uint32_t bqh[NQ][4], bql[NQ][4];
                uint32_t bb = stb + k16 * 16 * SB + ncol0 * 2 + laneB;
                #pragma unroll
                for (int q = 0; q < NQ; q++) {
                    ldsm4t(bqh[q], bb + q * 32);
                    ldsm4t(bql[q], bb + BLO + q * 32);
                }
                #pragma unroll
                for (int ms = 0; ms < 2; ms++)
                    #pragma unroll
                    for (int j = 0; j < NBJ; j++) {
                        const uint32_t* bh = &bqh[j >> 1][(j & 1) * 2];
                        const uint32_t* bl = &bql[j >> 1][(j & 1) * 2];
                        mma_bf16(acc[ms][j], ah[ms][kh], bh);
                        mma_bf16(acc[ms][j], al[ms][kh], bh);
                        mma_bf16(acc[ms][j], ah[ms][kh], bl);
                    }
            }
        }
        __syncthreads();
    }

    #pragma unroll
    for (int ms = 0; ms < 2; ms++)
        #pragma unroll
        for (int j = 0; j < NBJ; j++) {
            int r = row0 + rows0 + ms * 16 + fr;
            int c = ncol0 + j * 8 + fc;
            *(float2*)&Cpart[(size_t)r * NC + c] = make_float2(acc[ms][j][0], acc[ms][j][1]);
            *(float2*)&Cpart[(size_t)(r + 8) * NC + c] = make_float2(acc[ms][j][2], acc[ms][j][3]);
        }
}

__global__ __launch_bounds__(256, 2) void k_gemm(const float* __restrict__ roi,
                                                 const float* __restrict__ ctx,
                                                 const float* __restrict__ frm) {
    __shared__ __align__(128) uint8_t sm[4 * 64 * 144];   // 36864 B, max of both configs
    int b = blockIdx.x;
    if (b < 128) {
        gemm_core<64, false>(roi, nullptr, g_W1hi, g_W1lo,
                             g_C1part[b & 3], (b >> 2) * 128, (b & 3) * 1024, sm);
    } else {
        int u = b - 128;
        gemm_core<32, true>(frm, ctx, g_W2hi, g_W2lo,
                            g_C2part[u & 3], (u >> 2) * 128, (u & 3) * 1024, sm);
    }
}

// ---------------- k_mid: split-K reduce + bias + row softmax + transpose ----------------
__global__ void k_mid(const float* __restrict__ bcls, const float* __restrict__ br1,
                      const float* __restrict__ br2) {
    __shared__ float s1[128][65];
    int t = threadIdx.x;
    int n0 = blockIdx.x * 128;
    for (int i = t; i < 128 * 64; i += 128) {
        int r = i >> 6, c = i & 63;
        size_t o = (size_t)(n0 + r) * 64 + c;
        s1[r][c] = g_C1part[0][o] + g_C1part[1][o] + g_C1part[2][o] + g_C1part[3][o];
    }
    __syncthreads();
    int n = n0 + t;
    float v[21];
    {   // cls
        float m = -1e30f;
        for (int c = 0; c < 20; c++) { v[c] = s1[t][c] + bcls[c]; m = fmaxf(m, v[c]); }
        float ssum = 0.f;
        for (int c = 0; c < 20; c++) ssum += expf(v[c] - m);
        for (int c = 0; c < 20; c++) {
            g_clsST[c * NR + n] = v[c];
            g_clsPT[c * NR + n] = expf(v[c] - m) / ssum;
        }
    }
    {   // r1
        float m = -1e30f;
        for (int c = 0; c < 21; c++) { v[c] = s1[t][20 + c] + br1[c]; m = fmaxf(m, v[c]); }
        float ssum = 0.f;
        for (int c = 0; c < 21; c++) ssum += expf(v[c] - m);
        for (int c = 0; c < 21; c++) g_r1T[c * NR + n] = expf(v[c] - m) / ssum;
    }
    {   // r2
        float m = -1e30f;
        for (int c = 0; c < 21; c++) { v[c] = s1[t][41 + c] + br2[c]; m = fmaxf(m, v[c]); }
        float ssum = 0.f;
        for (int c = 0; c < 21; c++) ssum += expf(v[c] - m);
        for (int c = 0; c < 21; c++) g_r2T[c * NR + n] = expf(v[c] - m) / ssum;
    }
    __syncthreads();
    for (int i = t; i < 128 * 32; i += 128) {
        int r = i >> 5, c = i & 31;
        size_t o = (size_t)(n0 + r) * 32 + c;
        s1[r][c] = g_C2part[0][o] + g_C2part[1][o] + g_C2part[2][o] + g_C2part[3][o];
    }
    __syncthreads();
    for (int c = 0; c < 20; c++) g_detT[c * NR + n] = s1[t][c];
}

// ---------------- k_colreduce: per-class det softmax, dcs, two argmaxes ----------------
__global__ void k_colreduce(const float* __restrict__ ISw, const float* __restrict__ ss) {
    __shared__ float sred[1024];
    __shared__ int   sidx[1024];
    int c = blockIdx.x, t = threadIdx.x;
    float dv[4];
    float tmax = -1e30f;
    #pragma unroll
    for (int j = 0; j < 4; j++) {
        dv[j] = g_detT[c * NR + t + j * 1024];
        tmax = fmaxf(tmax, dv[j]);
    }
    sred[t] = tmax; __syncthreads();
    for (int s = 512; s > 0; s >>= 1) { if (t < s) sred[t] = fmaxf(sred[t], sred[t + s]); __syncthreads(); }
    float M = sred[0]; __syncthreads();

    float bs = 0.f;
    #pragma unroll
    for (int j = 0; j < 4; j++) { dv[j] = expf(dv[j] - M); bs += dv[j]; }
    sred[t] = bs; __syncthreads();
    for (int s = 512; s > 0; s >>= 1) { if (t < s) sred[t] += sred[t + s]; __syncthreads(); }
    float inv = 1.0f / sred[0]; __syncthreads();

    float dcs = 0.f, bv1 = -1e30f, bv2 = -1e30f;
    int bi1 = 0, bi2 = 0;
    #pragma unroll
    for (int j = 0; j < 4; j++) {
        int n = t + j * 1024;
        float dp = dv[j] * inv;
        dcs += g_clsST[c * NR + n] * dp;
        float w = ISw[n];
        float p1 = g_clsPT[c * NR + n] * dp * w;
        if (p1 > bv1) { bv1 = p1; bi1 = n; }
        float p2 = g_r1T[(c + 1) * NR + n] * w;
        if (p2 > bv2) { bv2 = p2; bi2 = n; }
    }
    sred[t] = dcs; __syncthreads();
    for (int s = 512; s > 0; s >>= 1) { if (t < s) sred[t] += sred[t + s]; __syncthreads(); }
    if (t == 0) g_dcs[c] = sred[0];
    __syncthreads();

    sred[t] = bv1; sidx[t] = bi1; __syncthreads();
    for (int s = 512; s > 0; s >>= 1) {
        if (t < s) {
            float v2 = sred[t + s]; int i2 = sidx[t + s];
            if (v2 > sred[t] || (v2 == sred[t] && i2 < sidx[t])) { sred[t] = v2; sidx[t] = i2; }
        }
        __syncthreads();
    }
    if (t == 0) {
        int i = sidx[0];
        g_boxes1[c * 4 + 0] = ss[i * 5 + 1]; g_boxes1[c * 4 + 1] = ss[i * 5 + 2];
        g_boxes1[c * 4 + 2] = ss[i * 5 + 3]; g_boxes1[c * 4 + 3] = ss[i * 5 + 4];
    }
    __syncthreads();

    sred[t] = bv2; sidx[t] = bi2; __syncthreads();
    for (int s = 512; s > 0; s >>= 1) {
        if (t < s) {
            float v2 = sred[t + s]; int i2 = sidx[t + s];
            if (v2 > sred[t] || (v2 == sred[t] && i2 < sidx[t])) { sred[t] = v2; sidx[t] = i2; }
        }
        __syncthreads();
    }
    if (t == 0) {
        int i = sidx[0];
        g_boxes2[c * 4 + 0] = ss[i * 5 + 1]; g_boxes2[c * 4 + 1] = ss[i * 5 + 2];
        g_boxes2[c * 4 + 2] = ss[i * 5 + 3]; g_boxes2[c * 4 + 3] = ss[i * 5 + 4];
    }
}

// ---------------- k_loss: per-row IoU supervision + NLL partials ----------------
__global__ void k_loss(const float* __restrict__ ss, const float* __restrict__ ISw,
                       const int* __restrict__ lab) {
    __shared__ float s0[256], s1[256], s2[256], s3[256];
    int tid = threadIdx.x;
    int n = blockIdx.x * 256 + tid;
    float x1 = ss[n * 5 + 1], y1 = ss[n * 5 + 2], x2 = ss[n * 5 + 3], y2 = ss[n * 5 + 4];
    float an = (x2 - x1 + 1.f) * (y2 - y1 + 1.f);
    float mo1 = -1.f, mo2 = -1.f;
    int gt1 = 0, gt2 = 0;
    #pragma unroll
    for (int c = 0; c < 20; c++) {
        if (lab[c] == 1) {
            {
                float qx1 = g_boxes1[c * 4 + 0], qy1 = g_boxes1[c * 4 + 1];
                float qx2 = g_boxes1[c * 4 + 2], qy2 = g_boxes1[c * 4 + 3];
                float iw = fmaxf(fminf(x2, qx2) - fmaxf(x1, qx1) + 1.f, 0.f);
                float ih = fmaxf(fminf(y2, qy2) - fmaxf(y1, qy1) + 1.f, 0.f);
                float inter = iw * ih;
                float aq = (qx2 - qx1 + 1.f) * (qy2 - qy1 + 1.f);
                float iou = inter / (an + aq - inter);
                if (iou > mo1) { mo1 = iou; gt1 = c; }
            }
            {
                float qx1 = g_boxes2[c * 4 + 0], qy1 = g_boxes2[c * 4 + 1];
                float qx2 = g_boxes2[c * 4 + 2], qy2 = g_boxes2[c * 4 + 3];
                float iw = fmaxf(fminf(x2, qx2) - fmaxf(x1, qx1) + 1.f, 0.f);
                float ih = fmaxf(fminf(y2, qy2) - fmaxf(y1, qy1) + 1.f, 0.f);
                float inter = iw * ih;
                float aq = (qx2 - qx1 + 1.f) * (qy2 - qy1 + 1.f);
                float iou = inter / (an + aq - inter);
                if (iou > mo2) { mo2 = iou; gt2 = c; }
            }
        }
    }
    float isw = ISw[n];
    bool fg1 = mo1 > 0.5f;
    bool keep1 = fg1 || (mo1 >= 0.1f && mo1 < 0.5f);
    int col1 = fg1 ? gt1 + 1 : 0;
    float l1 = keep1 ? isw * logf(g_r1T[col1 * NR + n]) : 0.f;
    float k1 = keep1 ? 1.f : 0.f;
    bool fg2 = mo2 > 0.5f;
    bool keep2 = fg2 || (mo2 >= 0.1f && mo2 < 0.5f);
    int col2 = fg2 ? gt2 + 1 : 0;
    float l2 = keep2 ? isw * logf(g_r2T[col2 * NR + n]) : 0.f;
    float k2 = keep2 ? 1.f : 0.f;

    s0[tid] = l1; s1[tid] = k1; s2[tid] = l2; s3[tid] = k2;
    __syncthreads();
    for (int s = 128; s > 0; s >>= 1) {
        if (tid < s) { s0[tid] += s0[tid + s]; s1[tid] += s1[tid + s];
                       s2[tid] += s2[tid + s]; s3[tid] += s3[tid + s]; }
        __syncthreads();
    }
    if (tid == 0) {
        g_lpart[blockIdx.x * 4 + 0] = s0[0];
        g_lpart[blockIdx.x * 4 + 1] = s1[0];
        g_lpart[blockIdx.x * 4 + 2] = s2[0];
        g_lpart[blockIdx.x * 4 + 3] = s3[0];
    }
}

// ---------------- k_final ----------------
__global__ void k_final(const int* __restrict__ lab, float* __restrict__ out) {
    if (threadIdx.x == 0) {
        float S1 = 0, N1 = 0, S2 = 0, N2 = 0;
        for (int b = 0; b < 16; b++) {
            S1 += g_lpart[b * 4 + 0]; N1 += g_lpart[b * 4 + 1];
            S2 += g_lpart[b * 4 + 2]; N2 += g_lpart[b * 4 + 3];
        }
        float cd = 0.f;
        for (int c = 0; c < 20; c++) {
            float l = (float)lab[c];
            cd += fmaxf(0.f, 1.f - l * g_dcs[c]);
        }
        cd /= 20.f;
        out[0] = cd + 0.1f * (-S1 / N1) + 0.1f * (-S2 / N2);
    }
}

extern "C" void kernel_launch(void* const* d_in, const int* in_sizes, int n_in,
                              void* d_out, int out_size) {
    const float* roi  = (const float*)d_in[0];
    const float* ctx  = (const float*)d_in[1];
    const float* frm  = (const float*)d_in[2];
    const float* Wcls = (const float*)d_in[3];
    const float* bcls = (const float*)d_in[4];
    const float* Wdet = (const float*)d_in[5];
    // d_in[6] = b_det: cancels in det_score
    const float* Wr1  = (const float*)d_in[7];
    const float* br1  = (const float*)d_in[8];
    const float* Wr2  = (const float*)d_in[9];
    const float* br2  = (const float*)d_in[10];
    const float* ss   = (const float*)d_in[11];
    const float* isw  = (const float*)d_in[12];
    const int*   lab  = (const int*)d_in[13];
    float* out = (float*)d_out;

    k_pack     <<<1536, 256>>>(Wcls, Wr1, Wr2, Wdet);
    k_gemm     <<<256, 256>>>(roi, ctx, frm);
    k_mid      <<<32, 128>>>(bcls, br1, br2);
    k_colreduce<<<20, 1024>>>(isw, ss);
    k_loss     <<<16, 256>>>(ss, isw, lab);
    k_final    <<<1, 32>>>(lab, out);
}